// round 1
// baseline (speedup 1.0000x reference)
#include <cuda_runtime.h>
#include <math.h>

#define B_  32
#define P_  196
#define D_  512
#define H_  8
#define U_  4
#define C_  500

#define KNOWN_ELEMS (16000LL * 11 * 512)   // 90,112,000
#define UNK_ELEMS   (32LL * 7 * 512)       // 114,688
#define ST_ELEMS    (32LL * 8 * 512)       // 131,072

// Scratch (device-global, allocation-free)
__device__ float g_pd[B_ * D_];            // projected_domain  [32,512]
__device__ float g_psem[B_ * H_ * D_];     // projected_sem     [32,8,512]

// ---------------------------------------------------------------------------
// K1: fused attention pooling. One block per b, 512 threads.
//   scores[p][h] = patch[b,p,:] . q[h,:]   (warp-cooperative dots)
//   softmax over p (per h), then semantic_tokens[b,h,d] = sum_p w[p][h]*patch
// ---------------------------------------------------------------------------
__global__ __launch_bounds__(512) void k_attn(
    const float* __restrict__ patch,   // [B,P,D]
    const float* __restrict__ qv,      // [H,D]
    float* __restrict__ st_out)        // [B,H,D]
{
    __shared__ float q_s[H_ * D_];     // 16 KB
    __shared__ float sc[P_][H_];       // 6.3 KB (scores -> weights in place)

    const int b    = blockIdx.x;
    const int tid  = threadIdx.x;
    const int warp = tid >> 5;
    const int lane = tid & 31;

    for (int i = tid; i < H_ * D_; i += 512) q_s[i] = qv[i];
    __syncthreads();

    const float* pb = patch + (size_t)b * P_ * D_;

    // Phase 1: scores. 16 warps stride over 196 rows.
    for (int p = warp; p < P_; p += 16) {
        const float* row = pb + p * D_;
        float acc[H_];
        #pragma unroll
        for (int h = 0; h < H_; h++) acc[h] = 0.f;
        for (int d = lane; d < D_; d += 32) {
            float v = row[d];
            #pragma unroll
            for (int h = 0; h < H_; h++) acc[h] = fmaf(v, q_s[h * D_ + d], acc[h]);
        }
        #pragma unroll
        for (int h = 0; h < H_; h++) {
            float a = acc[h];
            #pragma unroll
            for (int o = 16; o > 0; o >>= 1) a += __shfl_xor_sync(0xFFFFFFFFu, a, o);
            if (lane == 0) sc[p][h] = a;
        }
    }
    __syncthreads();

    // Phase 2: softmax over p (axis=1). Warp h handles head h.
    if (warp < H_) {
        const int h = warp;
        float m = -INFINITY;
        for (int p = lane; p < P_; p += 32) m = fmaxf(m, sc[p][h]);
        #pragma unroll
        for (int o = 16; o > 0; o >>= 1) m = fmaxf(m, __shfl_xor_sync(0xFFFFFFFFu, m, o));
        float s = 0.f;
        for (int p = lane; p < P_; p += 32) {
            float e = __expf(sc[p][h] - m);
            sc[p][h] = e;
            s += e;
        }
        #pragma unroll
        for (int o = 16; o > 0; o >>= 1) s += __shfl_xor_sync(0xFFFFFFFFu, s, o);
        float inv = 1.f / s;
        for (int p = lane; p < P_; p += 32) sc[p][h] *= inv;
    }
    __syncthreads();

    // Phase 3: weighted sum. Thread == d; 8 accumulators.
    const int d = tid;
    float acc[H_];
    #pragma unroll
    for (int h = 0; h < H_; h++) acc[h] = 0.f;
    for (int p = 0; p < P_; p++) {
        float v = pb[p * D_ + d];
        #pragma unroll
        for (int h = 0; h < H_; h++) acc[h] = fmaf(sc[p][h], v, acc[h]);
    }
    #pragma unroll
    for (int h = 0; h < H_; h++)
        st_out[((size_t)b * H_ + h) * D_ + d] = acc[h];
}

// ---------------------------------------------------------------------------
// K2: projected_domain[b,e] = gf[b,:] . dom_W[e,:] + dom_b[e]
// One block per b, thread == e, float4 inner loop.
// ---------------------------------------------------------------------------
__global__ __launch_bounds__(512) void k_dom(
    const float* __restrict__ gf,      // [B,D]
    const float* __restrict__ domW,    // [D,D] (row e contiguous in d)
    const float* __restrict__ domb)    // [D]
{
    __shared__ float4 gf_s[D_ / 4];
    const int b = blockIdx.x;
    const int e = threadIdx.x;

    const float4* gfr = (const float4*)(gf + (size_t)b * D_);
    for (int i = e; i < D_ / 4; i += 512) gf_s[i] = gfr[i];
    __syncthreads();

    const float4* wrow = (const float4*)(domW + (size_t)e * D_);
    float acc = 0.f;
    #pragma unroll 4
    for (int i = 0; i < D_ / 4; i++) {
        float4 w = wrow[i];
        float4 g = gf_s[i];
        acc = fmaf(g.x, w.x, acc);
        acc = fmaf(g.y, w.y, acc);
        acc = fmaf(g.z, w.z, acc);
        acc = fmaf(g.w, w.w, acc);
    }
    g_pd[(size_t)b * D_ + e] = acc + domb[e];
}

// ---------------------------------------------------------------------------
// K3: projected_sem[b,h,e] = st[b,h,:] . sem_W[h,e,:] + sem_b[h,e]
// Grid (eg=8, h=8, bg=2); block 512. 16 b-rows of st staged in smem.
// Each thread owns one e (8 threads share an e via broadcast LDG) and 2 b's.
// sem_W read only 2x total (16 MB) instead of 32x.
// ---------------------------------------------------------------------------
__global__ __launch_bounds__(512) void k_sem(
    const float* __restrict__ st,      // [B,H,D] (in d_out)
    const float* __restrict__ semW,    // [H,D,D]
    const float* __restrict__ semb)    // [H,D]
{
    __shared__ float st_s[16][D_ + 1]; // +1 pad to kill bank conflicts (32.1 KB)

    const int eg = blockIdx.x;         // 0..7 -> e range of 64
    const int h  = blockIdx.y;         // 0..7
    const int bg = blockIdx.z;         // 0..1 -> b range of 16
    const int tid = threadIdx.x;

    for (int i = tid; i < 16 * D_; i += 512) {
        int bb = i >> 9, d = i & (D_ - 1);
        st_s[bb][d] = st[(((size_t)(bg * 16 + bb)) * H_ + h) * D_ + d];
    }
    __syncthreads();

    const int e_local = tid >> 3;          // 0..63
    const int sub     = tid & 7;           // 0..7
    const int e       = eg * 64 + e_local;

    const float* wrow = semW + ((size_t)h * D_ + e) * D_;
    float acc0 = 0.f, acc1 = 0.f;
    #pragma unroll 4
    for (int d = 0; d < D_; d++) {
        float w = __ldg(wrow + d);
        acc0 = fmaf(st_s[sub][d],     w, acc0);
        acc1 = fmaf(st_s[sub + 8][d], w, acc1);
    }
    float bias = semb[h * D_ + e];
    const int b0 = bg * 16 + sub;
    g_psem[((size_t)b0 * H_ + h) * D_ + e]       = acc0 + bias;
    g_psem[((size_t)(b0 + 8) * H_ + h) * D_ + e] = acc1 + bias;
}

// ---------------------------------------------------------------------------
// K4: known_prompts writer. 360 MB of float4 stores (the roofline).
// Grid (cg=20, b=32); block 256. pd + psem for this b staged in smem once,
// then 25 prompt rows of (11 x 512) written per block.
//   t=0 : known_prefix[c]   t=1 : pd[b]   t=2..9 : psem[b,h]   t=10 : suffix[c]
// ---------------------------------------------------------------------------
__global__ __launch_bounds__(256) void k_known(
    const float* __restrict__ kpre,    // [C,1,D]
    const float* __restrict__ ksuf,    // [C,1,D]
    float* __restrict__ out)           // known region, [B*C, 11, D]
{
    __shared__ float4 sm4[9 * 128];    // [pd | psem h0..h7] as float4, 18 KB

    const int cg = blockIdx.x;         // 0..19  (25 c's each)
    const int b  = blockIdx.y;         // 0..31
    const int tid = threadIdx.x;

    {
        const float4* pd4 = (const float4*)(g_pd + (size_t)b * D_);
        const float4* ps4 = (const float4*)(g_psem + (size_t)b * H_ * D_);
        for (int i = tid; i < 9 * 128; i += 256)
            sm4[i] = (i < 128) ? pd4[i] : ps4[i - 128];
    }
    __syncthreads();

    float4* out4 = (float4*)out;
    const float4* pre4 = (const float4*)kpre;
    const float4* suf4 = (const float4*)ksuf;

    for (int cc = 0; cc < 25; cc++) {
        const int c = cg * 25 + cc;
        const size_t r = (size_t)b * C_ + c;
        float4* row4 = out4 + r * (11 * D_ / 4);   // 1408 float4 per row
        const float4* p4 = pre4 + (size_t)c * (D_ / 4);
        const float4* s4 = suf4 + (size_t)c * (D_ / 4);
        #pragma unroll
        for (int k = 0; k < 6; k++) {              // ceil(1408/256)
            int i = tid + k * 256;
            if (i < 1408) {
                int t = i >> 7, d4 = i & 127;      // warp-uniform t
                float4 v;
                if (t == 0)       v = p4[d4];
                else if (t == 10) v = s4[d4];
                else              v = sm4[(t - 1) * 128 + d4];
                row4[i] = v;
            }
        }
    }
}

// ---------------------------------------------------------------------------
// K5: unknown_prompts writer. [B, 7, D]. Trivial.
//   t=0 : unk_prefix   t=1 : pd[b]   t=2..5 : unknown_semantic_tokens   t=6 : unk_suffix
// ---------------------------------------------------------------------------
__global__ __launch_bounds__(256) void k_unk(
    const float* __restrict__ upre,
    const float* __restrict__ usuf,
    const float* __restrict__ ust,     // [U,D]
    float* __restrict__ out)           // unknown region
{
    const int b = blockIdx.x;
    const int tid = threadIdx.x;
    float4* out4 = (float4*)out + (size_t)b * (7 * D_ / 4);  // 896 float4
    const float4* upre4 = (const float4*)upre;
    const float4* usuf4 = (const float4*)usuf;
    const float4* ust4  = (const float4*)ust;
    const float4* pd4   = (const float4*)(g_pd + (size_t)b * D_);

    for (int i = tid; i < 896; i += 256) {
        int t = i >> 7, d4 = i & 127;
        float4 v;
        if (t == 0)      v = upre4[d4];
        else if (t == 1) v = pd4[d4];
        else if (t == 6) v = usuf4[d4];
        else             v = ust4[(t - 2) * 128 + d4];
        out4[i] = v;
    }
}

// ---------------------------------------------------------------------------
extern "C" void kernel_launch(void* const* d_in, const int* in_sizes, int n_in,
                              void* d_out, int out_size)
{
    const float* patch = (const float*)d_in[0];   // [B,P,D]
    const float* gf    = (const float*)d_in[1];   // [B,D]
    const float* qv    = (const float*)d_in[2];   // [H,D]
    const float* domW  = (const float*)d_in[3];   // [D,D]
    const float* domb  = (const float*)d_in[4];   // [D]
    const float* semW  = (const float*)d_in[5];   // [H,D,D]
    const float* semb  = (const float*)d_in[6];   // [H,D]
    const float* ust   = (const float*)d_in[7];   // [U,D]
    const float* kpre  = (const float*)d_in[8];   // [C,1,D]
    const float* ksuf  = (const float*)d_in[9];   // [C,1,D]
    const float* upre  = (const float*)d_in[10];  // [1,D]
    const float* usuf  = (const float*)d_in[11];  // [1,D]

    float* out     = (float*)d_out;
    float* unk_out = out + KNOWN_ELEMS;
    float* st_out  = out + KNOWN_ELEMS + UNK_ELEMS;

    k_attn<<<B_, 512>>>(patch, qv, st_out);
    k_dom<<<B_, 512>>>(gf, domW, domb);
    dim3 g3(8, 8, 2);
    k_sem<<<g3, 512>>>(st_out, semW, semb);
    dim3 g4(20, 32);
    k_known<<<g4, 256>>>(kpre, ksuf, out);
    k_unk<<<B_, 256>>>(upre, usuf, ust, unk_out);
}

// round 3
// speedup vs baseline: 1.3069x; 1.3069x over previous
#include <cuda_runtime.h>
#include <math.h>

#define B_  32
#define P_  196
#define D_  512
#define H_  8
#define U_  4
#define C_  500

#define KNOWN_ELEMS (16000LL * 11 * 512)   // 90,112,000
#define UNK_ELEMS   (32LL * 7 * 512)       // 114,688
#define ST_ELEMS    (32LL * 8 * 512)       // 131,072

// Scratch (device-global, allocation-free)
__device__ float g_pd[B_ * D_];            // projected_domain  [32,512]
__device__ float g_psem[B_ * H_ * D_];     // projected_sem     [32,8,512]
__device__ float g_w[B_ * P_ * H_];        // attention weights [32,196,8]

// ---------------------------------------------------------------------------
// K1a: scores[b,p,h] = patch[b,p,:] . q[h,:]
// Grid (b=32, pg=7), block 256 (8 warps). Warp per row, 28 rows per block.
// ---------------------------------------------------------------------------
__global__ __launch_bounds__(256) void k_scores(
    const float* __restrict__ patch,   // [B,P,D]
    const float* __restrict__ qv)      // [H,D]
{
    __shared__ float4 q_s4[H_ * 128];  // 16 KB

    const int b    = blockIdx.x;
    const int pg   = blockIdx.y;       // 0..6, 28 rows each
    const int tid  = threadIdx.x;
    const int warp = tid >> 5;
    const int lane = tid & 31;

    for (int i = tid; i < H_ * 128; i += 256) q_s4[i] = ((const float4*)qv)[i];
    __syncthreads();

    const float4* pb4 = (const float4*)(patch + (size_t)b * P_ * D_);

    #pragma unroll
    for (int it = 0; it < 4; it++) {
        const int row = it * 8 + warp;          // 0..31, valid if < 28
        if (row >= 28) break;
        const int p = pg * 28 + row;
        const float4* r4 = pb4 + (size_t)p * 128;

        float acc[H_];
        #pragma unroll
        for (int h = 0; h < H_; h++) acc[h] = 0.f;

        #pragma unroll
        for (int i2 = 0; i2 < 4; i2++) {
            float4 v = r4[i2 * 32 + lane];
            #pragma unroll
            for (int h = 0; h < H_; h++) {
                float4 q = q_s4[h * 128 + i2 * 32 + lane];
                acc[h] = fmaf(v.x, q.x, acc[h]);
                acc[h] = fmaf(v.y, q.y, acc[h]);
                acc[h] = fmaf(v.z, q.z, acc[h]);
                acc[h] = fmaf(v.w, q.w, acc[h]);
            }
        }
        #pragma unroll
        for (int h = 0; h < H_; h++) {
            float a = acc[h];
            #pragma unroll
            for (int o = 16; o > 0; o >>= 1) a += __shfl_xor_sync(0xFFFFFFFFu, a, o);
            acc[h] = a;
        }
        if (lane == 0) {
            #pragma unroll
            for (int h = 0; h < H_; h++)
                g_w[((size_t)b * P_ + p) * H_ + h] = acc[h];
        }
    }
}

// ---------------------------------------------------------------------------
// K1b: softmax over p for each (b,h). One block per b, 8 warps, warp per h.
// Normalizes g_w in place.
// ---------------------------------------------------------------------------
__global__ __launch_bounds__(256) void k_softmax()
{
    __shared__ float sc[P_][H_];
    const int b   = blockIdx.x;
    const int tid = threadIdx.x;
    const int warp = tid >> 5;
    const int lane = tid & 31;

    for (int i = tid; i < P_ * H_; i += 256) sc[i / H_][i % H_] = g_w[(size_t)b * P_ * H_ + i];
    __syncthreads();

    const int h = warp;
    float m = -INFINITY;
    for (int p = lane; p < P_; p += 32) m = fmaxf(m, sc[p][h]);
    #pragma unroll
    for (int o = 16; o > 0; o >>= 1) m = fmaxf(m, __shfl_xor_sync(0xFFFFFFFFu, m, o));
    float s = 0.f;
    for (int p = lane; p < P_; p += 32) {
        float e = __expf(sc[p][h] - m);
        sc[p][h] = e;
        s += e;
    }
    #pragma unroll
    for (int o = 16; o > 0; o >>= 1) s += __shfl_xor_sync(0xFFFFFFFFu, s, o);
    float inv = 1.f / s;
    for (int p = lane; p < P_; p += 32) sc[p][h] *= inv;
    __syncthreads();

    for (int i = tid; i < P_ * H_; i += 256) g_w[(size_t)b * P_ * H_ + i] = sc[i / H_][i % H_];
}

// ---------------------------------------------------------------------------
// K1c: pooling. semantic_tokens[b,h,d] = sum_p w[b,p,h] * patch[b,p,d]
// Grid (b=32, dg=4), block 128. Thread owns one d, 8 head accumulators.
// ---------------------------------------------------------------------------
__global__ __launch_bounds__(128) void k_pool(
    const float* __restrict__ patch,
    float* __restrict__ st_out)        // [B,H,D]
{
    __shared__ float w_s[P_][H_];      // 6.3 KB
    const int b  = blockIdx.x;
    const int dg = blockIdx.y;
    const int tid = threadIdx.x;
    const int d  = dg * 128 + tid;

    for (int i = tid; i < P_ * H_; i += 128) w_s[i / H_][i % H_] = g_w[(size_t)b * P_ * H_ + i];
    __syncthreads();

    const float* pb = patch + (size_t)b * P_ * D_;
    float acc[H_];
    #pragma unroll
    for (int h = 0; h < H_; h++) acc[h] = 0.f;

    #pragma unroll 2
    for (int p = 0; p < P_; p++) {
        float v = pb[(size_t)p * D_ + d];
        #pragma unroll
        for (int h = 0; h < H_; h++) acc[h] = fmaf(w_s[p][h], v, acc[h]);
    }
    #pragma unroll
    for (int h = 0; h < H_; h++)
        st_out[((size_t)b * H_ + h) * D_ + d] = acc[h];
}

// ---------------------------------------------------------------------------
// K2: projected_domain[b,e] = gf[b,:] . dom_W[e,:] + dom_b[e]
// ---------------------------------------------------------------------------
__global__ __launch_bounds__(512) void k_dom(
    const float* __restrict__ gf,      // [B,D]
    const float* __restrict__ domW,    // [D,D]
    const float* __restrict__ domb)    // [D]
{
    __shared__ float4 gf_s[D_ / 4];
    const int b = blockIdx.x;
    const int e = threadIdx.x;

    const float4* gfr = (const float4*)(gf + (size_t)b * D_);
    for (int i = e; i < D_ / 4; i += 512) gf_s[i] = gfr[i];
    __syncthreads();

    const float4* wrow = (const float4*)(domW + (size_t)e * D_);
    float acc = 0.f;
    #pragma unroll 4
    for (int i = 0; i < D_ / 4; i++) {
        float4 w = wrow[i];
        float4 g = gf_s[i];
        acc = fmaf(g.x, w.x, acc);
        acc = fmaf(g.y, w.y, acc);
        acc = fmaf(g.z, w.z, acc);
        acc = fmaf(g.w, w.w, acc);
    }
    g_pd[(size_t)b * D_ + e] = acc + domb[e];
}

// ---------------------------------------------------------------------------
// K3: projected_sem[b,h,e] = st[b,h,:] . sem_W[h,e,:] + sem_b[h,e]
// Coalesced smem-tiled version. Grid (eg=16, h=8), block 256 (8 warps).
// Per block: 32 e rows, all 32 b (two passes of 16 b staged in smem).
// Warp = (1 of 4 staged e rows) x (8 b). semW read 2x total = 16 MB.
// ---------------------------------------------------------------------------
__global__ __launch_bounds__(256) void k_sem(
    const float* __restrict__ st,      // [B,H,D]
    const float* __restrict__ semW,    // [H,D,D]
    const float* __restrict__ semb)    // [H,D]
{
    __shared__ float4 st4[16][128];    // 32 KB
    __shared__ float4 w4[4][128];      // 8 KB

    const int eg  = blockIdx.x;        // 0..15 -> 32 e each
    const int h   = blockIdx.y;        // 0..7
    const int tid = threadIdx.x;
    const int warp = tid >> 5;
    const int lane = tid & 31;
    const int e_sub = warp & 3;        // which staged e row
    const int bh    = warp >> 2;       // 0/1 -> b offset 0/8 in staged set

    const float4* st4g  = (const float4*)st;
    const float4* semW4 = (const float4*)semW;

    for (int bg = 0; bg < 2; bg++) {
        __syncthreads();
        // stage st for b = bg*16 .. bg*16+15 (this h)
        for (int i = tid; i < 16 * 128; i += 256) {
            int b_loc = i >> 7, d4 = i & 127;
            st4[b_loc][d4] = st4g[(((size_t)(bg * 16 + b_loc)) * H_ + h) * 128 + d4];
        }
        __syncthreads();

        for (int ei = 0; ei < 8; ei++) {
            __syncthreads();           // protect previous w4 use
            for (int i = tid; i < 4 * 128; i += 256) {
                int r = i >> 7, d4 = i & 127;
                int e = eg * 32 + ei * 4 + r;
                w4[r][d4] = semW4[((size_t)h * D_ + e) * 128 + d4];
            }
            __syncthreads();

            float acc[8];
            #pragma unroll
            for (int j = 0; j < 8; j++) acc[j] = 0.f;

            #pragma unroll
            for (int it = 0; it < 4; it++) {
                float4 w = w4[e_sub][it * 32 + lane];
                #pragma unroll
                for (int j = 0; j < 8; j++) {
                    float4 s = st4[bh * 8 + j][it * 32 + lane];
                    float a = acc[j];
                    a = fmaf(w.x, s.x, a);
                    a = fmaf(w.y, s.y, a);
                    a = fmaf(w.z, s.z, a);
                    a = fmaf(w.w, s.w, a);
                    acc[j] = a;
                }
            }
            #pragma unroll
            for (int j = 0; j < 8; j++) {
                float a = acc[j];
                #pragma unroll
                for (int o = 16; o > 0; o >>= 1) a += __shfl_xor_sync(0xFFFFFFFFu, a, o);
                acc[j] = a;
            }
            if (lane == 0) {
                const int e = eg * 32 + ei * 4 + e_sub;
                const float bias = semb[h * D_ + e];
                #pragma unroll
                for (int j = 0; j < 8; j++) {
                    const int b = bg * 16 + bh * 8 + j;
                    g_psem[((size_t)b * H_ + h) * D_ + e] = acc[j] + bias;
                }
            }
        }
    }
}

// ---------------------------------------------------------------------------
// K4: known_prompts writer (the roofline: ~360 MB of stores).
// Grid (cg=50, b=32) = 1600 blocks; 10 c's per block. Evict-first stores.
//   t=0 : known_prefix[c]  t=1 : pd[b]  t=2..9 : psem[b,h]  t=10 : suffix[c]
// ---------------------------------------------------------------------------
__global__ __launch_bounds__(256) void k_known(
    const float* __restrict__ kpre,    // [C,1,D]
    const float* __restrict__ ksuf,    // [C,1,D]
    float* __restrict__ out)           // [B*C, 11, D]
{
    __shared__ float4 sm4[9 * 128];    // [pd | psem h0..h7], 18 KB

    const int cg = blockIdx.x;         // 0..49 (10 c's each)
    const int b  = blockIdx.y;
    const int tid = threadIdx.x;

    {
        const float4* pd4 = (const float4*)(g_pd + (size_t)b * D_);
        const float4* ps4 = (const float4*)(g_psem + (size_t)b * H_ * D_);
        for (int i = tid; i < 9 * 128; i += 256)
            sm4[i] = (i < 128) ? pd4[i] : ps4[i - 128];
    }
    __syncthreads();

    float4* out4 = (float4*)out;
    const float4* pre4 = (const float4*)kpre;
    const float4* suf4 = (const float4*)ksuf;

    for (int cc = 0; cc < 10; cc++) {
        const int c = cg * 10 + cc;
        const size_t r = (size_t)b * C_ + c;
        float4* row4 = out4 + r * (11 * D_ / 4);   // 1408 float4 per row
        const float4* p4 = pre4 + (size_t)c * (D_ / 4);
        const float4* s4 = suf4 + (size_t)c * (D_ / 4);
        #pragma unroll
        for (int k = 0; k < 6; k++) {
            int i = tid + k * 256;
            if (i < 1408) {
                int t = i >> 7, d4 = i & 127;      // warp-uniform t
                float4 v;
                if (t == 0)       v = __ldg(p4 + d4);
                else if (t == 10) v = __ldg(s4 + d4);
                else              v = sm4[(t - 1) * 128 + d4];
                __stcs(row4 + i, v);
            }
        }
    }
}

// ---------------------------------------------------------------------------
// K5: unknown_prompts writer. [B, 7, D].
// ---------------------------------------------------------------------------
__global__ __launch_bounds__(256) void k_unk(
    const float* __restrict__ upre,
    const float* __restrict__ usuf,
    const float* __restrict__ ust,     // [U,D]
    float* __restrict__ out)
{
    const int b = blockIdx.x;
    const int tid = threadIdx.x;
    float4* out4 = (float4*)out + (size_t)b * (7 * D_ / 4);  // 896 float4
    const float4* upre4 = (const float4*)upre;
    const float4* usuf4 = (const float4*)usuf;
    const float4* ust4  = (const float4*)ust;
    const float4* pd4   = (const float4*)(g_pd + (size_t)b * D_);

    for (int i = tid; i < 896; i += 256) {
        int t = i >> 7, d4 = i & 127;
        float4 v;
        if (t == 0)      v = upre4[d4];
        else if (t == 1) v = pd4[d4];
        else if (t == 6) v = usuf4[d4];
        else             v = ust4[(t - 2) * 128 + d4];
        out4[i] = v;
    }
}

// ---------------------------------------------------------------------------
extern "C" void kernel_launch(void* const* d_in, const int* in_sizes, int n_in,
                              void* d_out, int out_size)
{
    const float* patch = (const float*)d_in[0];   // [B,P,D]
    const float* gf    = (const float*)d_in[1];   // [B,D]
    const float* qv    = (const float*)d_in[2];   // [H,D]
    const float* domW  = (const float*)d_in[3];   // [D,D]
    const float* domb  = (const float*)d_in[4];   // [D]
    const float* semW  = (const float*)d_in[5];   // [H,D,D]
    const float* semb  = (const float*)d_in[6];   // [H,D]
    const float* ust   = (const float*)d_in[7];   // [U,D]
    const float* kpre  = (const float*)d_in[8];   // [C,1,D]
    const float* ksuf  = (const float*)d_in[9];   // [C,1,D]
    const float* upre  = (const float*)d_in[10];  // [1,D]
    const float* usuf  = (const float*)d_in[11];  // [1,D]

    float* out     = (float*)d_out;
    float* unk_out = out + KNOWN_ELEMS;
    float* st_out  = out + KNOWN_ELEMS + UNK_ELEMS;

    dim3 g1(B_, 7);
    k_scores<<<g1, 256>>>(patch, qv);
    k_softmax<<<B_, 256>>>();
    dim3 g1c(B_, 4);
    k_pool<<<g1c, 128>>>(patch, st_out);
    k_dom<<<B_, 512>>>(gf, domW, domb);
    dim3 g3(16, 8);
    k_sem<<<g3, 256>>>(st_out, semW, semb);
    dim3 g4(50, 32);
    k_known<<<g4, 256>>>(kpre, ksuf, out);
    k_unk<<<B_, 256>>>(upre, usuf, ust, unk_out);
}

// round 7
// speedup vs baseline: 1.6399x; 1.2548x over previous
#include <cuda_runtime.h>
#include <math.h>

#define B_  32
#define P_  196
#define D_  512
#define H_  8
#define U_  4
#define C_  500

#define KNOWN_ELEMS (16000LL * 11 * 512)   // 90,112,000
#define UNK_ELEMS   (32LL * 7 * 512)       // 114,688
#define ST_ELEMS    (32LL * 8 * 512)       // 131,072

// Scratch (device-global, allocation-free)
__device__ float g_pd[B_ * D_];            // projected_domain  [32,512]
__device__ float g_psem[B_ * H_ * D_];     // projected_sem     [32,8,512]
__device__ float g_w[B_ * P_ * H_];        // attention weights [32,196,8]

// ---------------------------------------------------------------------------
// K1a: scores[b,p,h] = patch[b,p,:] . q[h,:]
// Grid (b=32, pg=7), block 256 (8 warps). Warp per row, 28 rows per block.
// ---------------------------------------------------------------------------
__global__ __launch_bounds__(256) void k_scores(
    const float* __restrict__ patch,   // [B,P,D]
    const float* __restrict__ qv)      // [H,D]
{
    __shared__ float4 q_s4[H_ * 128];  // 16 KB

    const int b    = blockIdx.x;
    const int pg   = blockIdx.y;       // 0..6, 28 rows each
    const int tid  = threadIdx.x;
    const int warp = tid >> 5;
    const int lane = tid & 31;

    for (int i = tid; i < H_ * 128; i += 256) q_s4[i] = ((const float4*)qv)[i];
    __syncthreads();

    const float4* pb4 = (const float4*)(patch + (size_t)b * P_ * D_);

    #pragma unroll
    for (int it = 0; it < 4; it++) {
        const int row = it * 8 + warp;          // 0..31, valid if < 28
        if (row >= 28) break;
        const int p = pg * 28 + row;
        const float4* r4 = pb4 + (size_t)p * 128;

        float acc[H_];
        #pragma unroll
        for (int h = 0; h < H_; h++) acc[h] = 0.f;

        #pragma unroll
        for (int i2 = 0; i2 < 4; i2++) {
            float4 v = r4[i2 * 32 + lane];
            #pragma unroll
            for (int h = 0; h < H_; h++) {
                float4 q = q_s4[h * 128 + i2 * 32 + lane];
                acc[h] = fmaf(v.x, q.x, acc[h]);
                acc[h] = fmaf(v.y, q.y, acc[h]);
                acc[h] = fmaf(v.z, q.z, acc[h]);
                acc[h] = fmaf(v.w, q.w, acc[h]);
            }
        }
        #pragma unroll
        for (int h = 0; h < H_; h++) {
            float a = acc[h];
            #pragma unroll
            for (int o = 16; o > 0; o >>= 1) a += __shfl_xor_sync(0xFFFFFFFFu, a, o);
            acc[h] = a;
        }
        if (lane == 0) {
            #pragma unroll
            for (int h = 0; h < H_; h++)
                g_w[((size_t)b * P_ + p) * H_ + h] = acc[h];
        }
    }
}

// ---------------------------------------------------------------------------
// K1b: softmax over p for each (b,h). One block per b, 8 warps, warp per h.
// ---------------------------------------------------------------------------
__global__ __launch_bounds__(256) void k_softmax()
{
    __shared__ float sc[P_][H_];
    const int b   = blockIdx.x;
    const int tid = threadIdx.x;
    const int warp = tid >> 5;
    const int lane = tid & 31;

    for (int i = tid; i < P_ * H_; i += 256) sc[i / H_][i % H_] = g_w[(size_t)b * P_ * H_ + i];
    __syncthreads();

    const int h = warp;
    float m = -INFINITY;
    for (int p = lane; p < P_; p += 32) m = fmaxf(m, sc[p][h]);
    #pragma unroll
    for (int o = 16; o > 0; o >>= 1) m = fmaxf(m, __shfl_xor_sync(0xFFFFFFFFu, m, o));
    float s = 0.f;
    for (int p = lane; p < P_; p += 32) {
        float e = __expf(sc[p][h] - m);
        sc[p][h] = e;
        s += e;
    }
    #pragma unroll
    for (int o = 16; o > 0; o >>= 1) s += __shfl_xor_sync(0xFFFFFFFFu, s, o);
    float inv = 1.f / s;
    for (int p = lane; p < P_; p += 32) sc[p][h] *= inv;
    __syncthreads();

    for (int i = tid; i < P_ * H_; i += 256) g_w[(size_t)b * P_ * H_ + i] = sc[i / H_][i % H_];
}

// ---------------------------------------------------------------------------
// K1c: pooling. semantic_tokens[b,h,d] = sum_p w[b,p,h] * patch[b,p,d]
// Grid (b=32, dg=4), block 128.
// ---------------------------------------------------------------------------
__global__ __launch_bounds__(128) void k_pool(
    const float* __restrict__ patch,
    float* __restrict__ st_out)        // [B,H,D]
{
    __shared__ float w_s[P_][H_];      // 6.3 KB
    const int b  = blockIdx.x;
    const int dg = blockIdx.y;
    const int tid = threadIdx.x;
    const int d  = dg * 128 + tid;

    for (int i = tid; i < P_ * H_; i += 128) w_s[i / H_][i % H_] = g_w[(size_t)b * P_ * H_ + i];
    __syncthreads();

    const float* pb = patch + (size_t)b * P_ * D_;
    float acc[H_];
    #pragma unroll
    for (int h = 0; h < H_; h++) acc[h] = 0.f;

    #pragma unroll 2
    for (int p = 0; p < P_; p++) {
        float v = pb[(size_t)p * D_ + d];
        #pragma unroll
        for (int h = 0; h < H_; h++) acc[h] = fmaf(w_s[p][h], v, acc[h]);
    }
    #pragma unroll
    for (int h = 0; h < H_; h++)
        st_out[((size_t)b * H_ + h) * D_ + d] = acc[h];
}

// ---------------------------------------------------------------------------
// K3: fused sem + dom projections.
// hh in [0,8): psem[b,hh,e] = st[b,hh,:] . sem_W[hh,e,:] + sem_b[hh,e]
// hh == 8  : pd[b,e]       = gf[b,:]    . dom_W[e,:]     + dom_b[e]
// Grid (eg=16, hh=9) = 144 blocks, block 256 (8 warps).
// Per block: 32 e rows, all 32 b (two passes of 16 b staged in smem).
// Warp = (1 of 4 staged e rows) x (8 b). Weights read 2x total.
// ---------------------------------------------------------------------------
__global__ __launch_bounds__(256) void k_semdom(
    const float* __restrict__ st,      // [B,H,D]
    const float* __restrict__ semW,    // [H,D,D]
    const float* __restrict__ semb,    // [H,D]
    const float* __restrict__ gf,      // [B,D]
    const float* __restrict__ domW,    // [D,D]
    const float* __restrict__ domb)    // [D]
{
    __shared__ float4 st4[16][128];    // 32 KB
    __shared__ float4 w4[4][128];      // 8 KB

    const int eg  = blockIdx.x;        // 0..15 -> 32 e each
    const int hh  = blockIdx.y;        // 0..8 (8 == domain)
    const int tid = threadIdx.x;
    const int warp = tid >> 5;
    const int lane = tid & 31;
    const int e_sub = warp & 3;        // which staged e row
    const int bh    = warp >> 2;       // 0/1 -> b offset 0/8 in staged set

    const bool is_dom = (hh == H_);
    const float4* src4  = is_dom ? (const float4*)gf : (const float4*)st;
    const float4* W4    = is_dom ? (const float4*)domW
                                 : (const float4*)semW + (size_t)hh * D_ * 128;
    const float*  bias_p = is_dom ? domb : (semb + hh * D_);
    float* outp = is_dom ? g_pd : g_psem;

    for (int bg = 0; bg < 2; bg++) {
        __syncthreads();
        // stage source rows for b = bg*16 .. bg*16+15
        for (int i = tid; i < 16 * 128; i += 256) {
            int b_loc = i >> 7, d4 = i & 127;
            int b = bg * 16 + b_loc;
            size_t off = is_dom ? ((size_t)b * 128 + d4)
                                : (((size_t)b * H_ + hh) * 128 + d4);
            st4[b_loc][d4] = src4[off];
        }
        __syncthreads();

        for (int ei = 0; ei < 8; ei++) {
            __syncthreads();           // protect previous w4 use
            for (int i = tid; i < 4 * 128; i += 256) {
                int r = i >> 7, d4 = i & 127;
                int e = eg * 32 + ei * 4 + r;
                w4[r][d4] = W4[(size_t)e * 128 + d4];
            }
            __syncthreads();

            float acc[8];
            #pragma unroll
            for (int j = 0; j < 8; j++) acc[j] = 0.f;

            #pragma unroll
            for (int it = 0; it < 4; it++) {
                float4 w = w4[e_sub][it * 32 + lane];
                #pragma unroll
                for (int j = 0; j < 8; j++) {
                    float4 s = st4[bh * 8 + j][it * 32 + lane];
                    float a = acc[j];
                    a = fmaf(w.x, s.x, a);
                    a = fmaf(w.y, s.y, a);
                    a = fmaf(w.z, s.z, a);
                    a = fmaf(w.w, s.w, a);
                    acc[j] = a;
                }
            }
            #pragma unroll
            for (int j = 0; j < 8; j++) {
                float a = acc[j];
                #pragma unroll
                for (int o = 16; o > 0; o >>= 1) a += __shfl_xor_sync(0xFFFFFFFFu, a, o);
                acc[j] = a;
            }
            if (lane == 0) {
                const int e = eg * 32 + ei * 4 + e_sub;
                const float bias = bias_p[e];
                #pragma unroll
                for (int j = 0; j < 8; j++) {
                    const int b = bg * 16 + bh * 8 + j;
                    size_t off = is_dom ? ((size_t)b * D_ + e)
                                        : (((size_t)b * H_ + hh) * D_ + e);
                    outp[off] = acc[j] + bias;
                }
            }
        }
    }
}

// ---------------------------------------------------------------------------
// K4: known_prompts writer (the roofline: ~360 MB of stores).
// Grid (cg=50, b=32) = 1600 blocks; 10 c's per block. Evict-first stores.
//   t=0 : known_prefix[c]  t=1 : pd[b]  t=2..9 : psem[b,h]  t=10 : suffix[c]
// ---------------------------------------------------------------------------
__global__ __launch_bounds__(256) void k_known(
    const float* __restrict__ kpre,    // [C,1,D]
    const float* __restrict__ ksuf,    // [C,1,D]
    float* __restrict__ out)           // [B*C, 11, D]
{
    __shared__ float4 sm4[9 * 128];    // [pd | psem h0..h7], 18 KB

    const int cg = blockIdx.x;         // 0..49 (10 c's each)
    const int b  = blockIdx.y;
    const int tid = threadIdx.x;

    {
        const float4* pd4 = (const float4*)(g_pd + (size_t)b * D_);
        const float4* ps4 = (const float4*)(g_psem + (size_t)b * H_ * D_);
        for (int i = tid; i < 9 * 128; i += 256)
            sm4[i] = (i < 128) ? pd4[i] : ps4[i - 128];
    }
    __syncthreads();

    float4* out4 = (float4*)out;
    const float4* pre4 = (const float4*)kpre;
    const float4* suf4 = (const float4*)ksuf;

    for (int cc = 0; cc < 10; cc++) {
        const int c = cg * 10 + cc;
        const size_t r = (size_t)b * C_ + c;
        float4* row4 = out4 + r * (11 * D_ / 4);   // 1408 float4 per row
        const float4* p4 = pre4 + (size_t)c * (D_ / 4);
        const float4* s4 = suf4 + (size_t)c * (D_ / 4);
        #pragma unroll
        for (int k = 0; k < 6; k++) {
            int i = tid + k * 256;
            if (i < 1408) {
                int t = i >> 7, d4 = i & 127;      // warp-uniform t
                float4 v;
                if (t == 0)       v = __ldg(p4 + d4);
                else if (t == 10) v = __ldg(s4 + d4);
                else              v = sm4[(t - 1) * 128 + d4];
                __stcs(row4 + i, v);
            }
        }
    }
}

// ---------------------------------------------------------------------------
// K5: unknown_prompts writer. [B, 7, D].
// ---------------------------------------------------------------------------
__global__ __launch_bounds__(256) void k_unk(
    const float* __restrict__ upre,
    const float* __restrict__ usuf,
    const float* __restrict__ ust,     // [U,D]
    float* __restrict__ out)
{
    const int b = blockIdx.x;
    const int tid = threadIdx.x;
    float4* out4 = (float4*)out + (size_t)b * (7 * D_ / 4);  // 896 float4
    const float4* upre4 = (const float4*)upre;
    const float4* usuf4 = (const float4*)usuf;
    const float4* ust4  = (const float4*)ust;
    const float4* pd4   = (const float4*)(g_pd + (size_t)b * D_);

    for (int i = tid; i < 896; i += 256) {
        int t = i >> 7, d4 = i & 127;
        float4 v;
        if (t == 0)      v = upre4[d4];
        else if (t == 1) v = pd4[d4];
        else if (t == 6) v = usuf4[d4];
        else             v = ust4[(t - 2) * 128 + d4];
        out4[i] = v;
    }
}

// ---------------------------------------------------------------------------
extern "C" void kernel_launch(void* const* d_in, const int* in_sizes, int n_in,
                              void* d_out, int out_size)
{
    const float* patch = (const float*)d_in[0];   // [B,P,D]
    const float* gf    = (const float*)d_in[1];   // [B,D]
    const float* qv    = (const float*)d_in[2];   // [H,D]
    const float* domW  = (const float*)d_in[3];   // [D,D]
    const float* domb  = (const float*)d_in[4];   // [D]
    const float* semW  = (const float*)d_in[5];   // [H,D,D]
    const float* semb  = (const float*)d_in[6];   // [H,D]
    const float* ust   = (const float*)d_in[7];   // [U,D]
    const float* kpre  = (const float*)d_in[8];   // [C,1,D]
    const float* ksuf  = (const float*)d_in[9];   // [C,1,D]
    const float* upre  = (const float*)d_in[10];  // [1,D]
    const float* usuf  = (const float*)d_in[11];  // [1,D]

    float* out     = (float*)d_out;
    float* unk_out = out + KNOWN_ELEMS;
    float* st_out  = out + KNOWN_ELEMS + UNK_ELEMS;

    dim3 g1(B_, 7);
    k_scores<<<g1, 256>>>(patch, qv);
    k_softmax<<<B_, 256>>>();
    dim3 g1c(B_, 4);
    k_pool<<<g1c, 128>>>(patch, st_out);
    dim3 g3(16, 9);
    k_semdom<<<g3, 256>>>(st_out, semW, semb, gf, domW, domb);
    dim3 g4(50, 32);
    k_known<<<g4, 256>>>(kpre, ksuf, out);
    k_unk<<<B_, 256>>>(upre, usuf, ust, unk_out);
}

// round 12
// speedup vs baseline: 1.7865x; 1.0894x over previous
#include <cuda_runtime.h>
#include <math.h>

#define B_  32
#define P_  196
#define D_  512
#define H_  8
#define U_  4
#define C_  500

#define KNOWN_ELEMS (16000LL * 11 * 512)   // 90,112,000
#define UNK_ELEMS   (32LL * 7 * 512)       // 114,688
#define ST_ELEMS    (32LL * 8 * 512)       // 131,072

// Scratch (device-global, allocation-free)
__device__ float g_pd[B_ * D_];            // projected_domain  [32,512]
__device__ float g_psem[B_ * H_ * D_];     // projected_sem     [32,8,512]
__device__ float g_w[B_ * P_ * H_];        // attention weights [32,196,8]

// ---------------------------------------------------------------------------
// K1a: scores[b,p,h] = patch[b,p,:] . q[h,:]
// Grid (b=32, pg=7), block 256 (8 warps). Warp per row, 28 rows per block.
// ---------------------------------------------------------------------------
__global__ __launch_bounds__(256) void k_scores(
    const float* __restrict__ patch,   // [B,P,D]
    const float* __restrict__ qv)      // [H,D]
{
    __shared__ float4 q_s4[H_ * 128];  // 16 KB

    const int b    = blockIdx.x;
    const int pg   = blockIdx.y;       // 0..6, 28 rows each
    const int tid  = threadIdx.x;
    const int warp = tid >> 5;
    const int lane = tid & 31;

    for (int i = tid; i < H_ * 128; i += 256) q_s4[i] = ((const float4*)qv)[i];
    __syncthreads();

    const float4* pb4 = (const float4*)(patch + (size_t)b * P_ * D_);

    #pragma unroll
    for (int it = 0; it < 4; it++) {
        const int row = it * 8 + warp;          // 0..31, valid if < 28
        if (row >= 28) break;
        const int p = pg * 28 + row;
        const float4* r4 = pb4 + (size_t)p * 128;

        float acc[H_];
        #pragma unroll
        for (int h = 0; h < H_; h++) acc[h] = 0.f;

        #pragma unroll
        for (int i2 = 0; i2 < 4; i2++) {
            float4 v = r4[i2 * 32 + lane];
            #pragma unroll
            for (int h = 0; h < H_; h++) {
                float4 q = q_s4[h * 128 + i2 * 32 + lane];
                acc[h] = fmaf(v.x, q.x, acc[h]);
                acc[h] = fmaf(v.y, q.y, acc[h]);
                acc[h] = fmaf(v.z, q.z, acc[h]);
                acc[h] = fmaf(v.w, q.w, acc[h]);
            }
        }
        #pragma unroll
        for (int h = 0; h < H_; h++) {
            float a = acc[h];
            #pragma unroll
            for (int o = 16; o > 0; o >>= 1) a += __shfl_xor_sync(0xFFFFFFFFu, a, o);
            acc[h] = a;
        }
        if (lane == 0) {
            #pragma unroll
            for (int h = 0; h < H_; h++)
                g_w[((size_t)b * P_ + p) * H_ + h] = acc[h];
        }
    }
}

// ---------------------------------------------------------------------------
// K1b: softmax over p for each (b,h). One block per b, 8 warps, warp per h.
// ---------------------------------------------------------------------------
__global__ __launch_bounds__(256) void k_softmax()
{
    __shared__ float sc[P_][H_];
    const int b   = blockIdx.x;
    const int tid = threadIdx.x;
    const int warp = tid >> 5;
    const int lane = tid & 31;

    for (int i = tid; i < P_ * H_; i += 256) sc[i / H_][i % H_] = g_w[(size_t)b * P_ * H_ + i];
    __syncthreads();

    const int h = warp;
    float m = -INFINITY;
    for (int p = lane; p < P_; p += 32) m = fmaxf(m, sc[p][h]);
    #pragma unroll
    for (int o = 16; o > 0; o >>= 1) m = fmaxf(m, __shfl_xor_sync(0xFFFFFFFFu, m, o));
    float s = 0.f;
    for (int p = lane; p < P_; p += 32) {
        float e = __expf(sc[p][h] - m);
        sc[p][h] = e;
        s += e;
    }
    #pragma unroll
    for (int o = 16; o > 0; o >>= 1) s += __shfl_xor_sync(0xFFFFFFFFu, s, o);
    float inv = 1.f / s;
    for (int p = lane; p < P_; p += 32) sc[p][h] *= inv;
    __syncthreads();

    for (int i = tid; i < P_ * H_; i += 256) g_w[(size_t)b * P_ * H_ + i] = sc[i / H_][i % H_];
}

// ---------------------------------------------------------------------------
// K1c: pooling. semantic_tokens[b,h,d] = sum_p w[b,p,h] * patch[b,p,d]
// Grid (b=32, dg=4), block 128.
// ---------------------------------------------------------------------------
__global__ __launch_bounds__(128) void k_pool(
    const float* __restrict__ patch,
    float* __restrict__ st_out)        // [B,H,D]
{
    __shared__ float w_s[P_][H_];      // 6.3 KB
    const int b  = blockIdx.x;
    const int dg = blockIdx.y;
    const int tid = threadIdx.x;
    const int d  = dg * 128 + tid;

    for (int i = tid; i < P_ * H_; i += 128) w_s[i / H_][i % H_] = g_w[(size_t)b * P_ * H_ + i];
    __syncthreads();

    const float* pb = patch + (size_t)b * P_ * D_;
    float acc[H_];
    #pragma unroll
    for (int h = 0; h < H_; h++) acc[h] = 0.f;

    #pragma unroll 2
    for (int p = 0; p < P_; p++) {
        float v = pb[(size_t)p * D_ + d];
        #pragma unroll
        for (int h = 0; h < H_; h++) acc[h] = fmaf(w_s[p][h], v, acc[h]);
    }
    #pragma unroll
    for (int h = 0; h < H_; h++)
        st_out[((size_t)b * H_ + h) * D_ + d] = acc[h];
}

// ---------------------------------------------------------------------------
// K3: fused sem + dom projections, warp-per-e-row version.
// hh in [0,8): psem[b,hh,e] = st[b,hh,:] . sem_W[hh,e,:] + sem_b[hh,e]
// hh == 8  : pd[b,e]       = gf[b,:]    . dom_W[e,:]     + dom_b[e]
// Grid (eg=64, hh=9, bg=4) = 2304 blocks; block 256 (8 warps).
// Block stages st for 8 b's (16 KB). Warp w owns e = eg*8+w; lanes load the
// W row coalesced (4 front-batched LDG.128, no barriers), FMA vs 8 b's.
// W rows read 4x total (~33 MB) but W is 8.25 MB -> L2-resident.
// ---------------------------------------------------------------------------
__global__ __launch_bounds__(256) void k_semdom(
    const float* __restrict__ st,      // [B,H,D]
    const float* __restrict__ semW,    // [H,D,D]
    const float* __restrict__ semb,    // [H,D]
    const float* __restrict__ gf,      // [B,D]
    const float* __restrict__ domW,    // [D,D]
    const float* __restrict__ domb)    // [D]
{
    __shared__ float4 st4[8][128];     // 16 KB

    const int eg  = blockIdx.x;        // 0..63 -> 8 e each
    const int hh  = blockIdx.y;        // 0..8 (8 == domain)
    const int bg  = blockIdx.z;        // 0..3 -> 8 b each
    const int tid = threadIdx.x;
    const int warp = tid >> 5;
    const int lane = tid & 31;

    const bool is_dom = (hh == H_);
    const float4* src4 = is_dom ? (const float4*)gf : (const float4*)st;
    const float4* W4   = is_dom ? (const float4*)domW
                                : (const float4*)semW + (size_t)hh * D_ * 128;
    const float* bias_p = is_dom ? domb : (semb + hh * D_);
    float* outp = is_dom ? g_pd : g_psem;

    // stage st for b = bg*8 .. bg*8+7 (this hh)
    for (int i = tid; i < 8 * 128; i += 256) {
        int b_loc = i >> 7, d4 = i & 127;
        int b = bg * 8 + b_loc;
        size_t off = is_dom ? ((size_t)b * 128 + d4)
                            : (((size_t)b * H_ + hh) * 128 + d4);
        st4[b_loc][d4] = src4[off];
    }
    __syncthreads();

    const int e = eg * 8 + warp;
    const float4* wrow = W4 + (size_t)e * 128;

    // front-batched coalesced weight loads: MLP=4
    float4 wv[4];
    #pragma unroll
    for (int it = 0; it < 4; it++) wv[it] = __ldg(wrow + it * 32 + lane);

    float acc[8];
    #pragma unroll
    for (int j = 0; j < 8; j++) acc[j] = 0.f;

    #pragma unroll
    for (int it = 0; it < 4; it++) {
        #pragma unroll
        for (int j = 0; j < 8; j++) {
            float4 s = st4[j][it * 32 + lane];
            float a = acc[j];
            a = fmaf(wv[it].x, s.x, a);
            a = fmaf(wv[it].y, s.y, a);
            a = fmaf(wv[it].z, s.z, a);
            a = fmaf(wv[it].w, s.w, a);
            acc[j] = a;
        }
    }
    #pragma unroll
    for (int j = 0; j < 8; j++) {
        float a = acc[j];
        #pragma unroll
        for (int o = 16; o > 0; o >>= 1) a += __shfl_xor_sync(0xFFFFFFFFu, a, o);
        acc[j] = a;
    }
    if (lane == 0) {
        const float bias = bias_p[e];
        #pragma unroll
        for (int j = 0; j < 8; j++) {
            const int b = bg * 8 + j;
            size_t off = is_dom ? ((size_t)b * D_ + e)
                                : (((size_t)b * H_ + hh) * D_ + e);
            outp[off] = acc[j] + bias;
        }
    }
}

// ---------------------------------------------------------------------------
// K4: known_prompts writer (the roofline: ~360 MB of stores).
// Grid (cg=50, b=32) = 1600 blocks; 10 c's per block. Evict-first stores.
//   t=0 : known_prefix[c]  t=1 : pd[b]  t=2..9 : psem[b,h]  t=10 : suffix[c]
// ---------------------------------------------------------------------------
__global__ __launch_bounds__(256) void k_known(
    const float* __restrict__ kpre,    // [C,1,D]
    const float* __restrict__ ksuf,    // [C,1,D]
    float* __restrict__ out)           // [B*C, 11, D]
{
    __shared__ float4 sm4[9 * 128];    // [pd | psem h0..h7], 18 KB

    const int cg = blockIdx.x;         // 0..49 (10 c's each)
    const int b  = blockIdx.y;
    const int tid = threadIdx.x;

    {
        const float4* pd4 = (const float4*)(g_pd + (size_t)b * D_);
        const float4* ps4 = (const float4*)(g_psem + (size_t)b * H_ * D_);
        for (int i = tid; i < 9 * 128; i += 256)
            sm4[i] = (i < 128) ? pd4[i] : ps4[i - 128];
    }
    __syncthreads();

    float4* out4 = (float4*)out;
    const float4* pre4 = (const float4*)kpre;
    const float4* suf4 = (const float4*)ksuf;

    for (int cc = 0; cc < 10; cc++) {
        const int c = cg * 10 + cc;
        const size_t r = (size_t)b * C_ + c;
        float4* row4 = out4 + r * (11 * D_ / 4);   // 1408 float4 per row
        const float4* p4 = pre4 + (size_t)c * (D_ / 4);
        const float4* s4 = suf4 + (size_t)c * (D_ / 4);
        #pragma unroll
        for (int k = 0; k < 6; k++) {
            int i = tid + k * 256;
            if (i < 1408) {
                int t = i >> 7, d4 = i & 127;      // warp-uniform t
                float4 v;
                if (t == 0)       v = __ldg(p4 + d4);
                else if (t == 10) v = __ldg(s4 + d4);
                else              v = sm4[(t - 1) * 128 + d4];
                __stcs(row4 + i, v);
            }
        }
    }
}

// ---------------------------------------------------------------------------
// K5: unknown_prompts writer. [B, 7, D].
// ---------------------------------------------------------------------------
__global__ __launch_bounds__(256) void k_unk(
    const float* __restrict__ upre,
    const float* __restrict__ usuf,
    const float* __restrict__ ust,     // [U,D]
    float* __restrict__ out)
{
    const int b = blockIdx.x;
    const int tid = threadIdx.x;
    float4* out4 = (float4*)out + (size_t)b * (7 * D_ / 4);  // 896 float4
    const float4* upre4 = (const float4*)upre;
    const float4* usuf4 = (const float4*)usuf;
    const float4* ust4  = (const float4*)ust;
    const float4* pd4   = (const float4*)(g_pd + (size_t)b * D_);

    for (int i = tid; i < 896; i += 256) {
        int t = i >> 7, d4 = i & 127;
        float4 v;
        if (t == 0)      v = upre4[d4];
        else if (t == 1) v = pd4[d4];
        else if (t == 6) v = usuf4[d4];
        else             v = ust4[(t - 2) * 128 + d4];
        out4[i] = v;
    }
}

// ---------------------------------------------------------------------------
extern "C" void kernel_launch(void* const* d_in, const int* in_sizes, int n_in,
                              void* d_out, int out_size)
{
    const float* patch = (const float*)d_in[0];   // [B,P,D]
    const float* gf    = (const float*)d_in[1];   // [B,D]
    const float* qv    = (const float*)d_in[2];   // [H,D]
    const float* domW  = (const float*)d_in[3];   // [D,D]
    const float* domb  = (const float*)d_in[4];   // [D]
    const float* semW  = (const float*)d_in[5];   // [H,D,D]
    const float* semb  = (const float*)d_in[6];   // [H,D]
    const float* ust   = (const float*)d_in[7];   // [U,D]
    const float* kpre  = (const float*)d_in[8];   // [C,1,D]
    const float* ksuf  = (const float*)d_in[9];   // [C,1,D]
    const float* upre  = (const float*)d_in[10];  // [1,D]
    const float* usuf  = (const float*)d_in[11];  // [1,D]

    float* out     = (float*)d_out;
    float* unk_out = out + KNOWN_ELEMS;
    float* st_out  = out + KNOWN_ELEMS + UNK_ELEMS;

    dim3 g1(B_, 7);
    k_scores<<<g1, 256>>>(patch, qv);
    k_softmax<<<B_, 256>>>();
    dim3 g1c(B_, 4);
    k_pool<<<g1c, 128>>>(patch, st_out);
    dim3 g3(64, 9, 4);
    k_semdom<<<g3, 256>>>(st_out, semW, semb, gf, domW, domb);
    dim3 g4(50, 32);
    k_known<<<g4, 256>>>(kpre, ksuf, out);
    k_unk<<<B_, 256>>>(upre, usuf, ust, unk_out);
}

// round 13
// speedup vs baseline: 1.8559x; 1.0389x over previous
#include <cuda_runtime.h>
#include <math.h>

#define B_  32
#define P_  196
#define D_  512
#define H_  8
#define U_  4
#define C_  500

#define KNOWN_ELEMS (16000LL * 11 * 512)   // 90,112,000
#define UNK_ELEMS   (32LL * 7 * 512)       // 114,688
#define ST_ELEMS    (32LL * 8 * 512)       // 131,072

// Scratch (device-global, allocation-free)
__device__ float g_pd[B_ * D_];            // projected_domain  [32,512]
__device__ float g_psem[B_ * H_ * D_];     // projected_sem     [32,8,512]
__device__ float g_w[B_ * P_ * H_];        // raw attention scores [32,196,8]

// ---------------------------------------------------------------------------
// K1a: scores[b,p,h] = patch[b,p,:] . q[h,:]   (raw, softmax done in k_pool)
// Grid (b=32, pg=7), block 256 (8 warps). Warp per row, 28 rows per block.
// ---------------------------------------------------------------------------
__global__ __launch_bounds__(256) void k_scores(
    const float* __restrict__ patch,   // [B,P,D]
    const float* __restrict__ qv)      // [H,D]
{
    __shared__ float4 q_s4[H_ * 128];  // 16 KB

    const int b    = blockIdx.x;
    const int pg   = blockIdx.y;       // 0..6, 28 rows each
    const int tid  = threadIdx.x;
    const int warp = tid >> 5;
    const int lane = tid & 31;

    for (int i = tid; i < H_ * 128; i += 256) q_s4[i] = ((const float4*)qv)[i];
    __syncthreads();

    const float4* pb4 = (const float4*)(patch + (size_t)b * P_ * D_);

    #pragma unroll
    for (int it = 0; it < 4; it++) {
        const int row = it * 8 + warp;          // 0..31, valid if < 28
        if (row >= 28) break;
        const int p = pg * 28 + row;
        const float4* r4 = pb4 + (size_t)p * 128;

        // front-batch the 4 row loads (MLP=4)
        float4 v[4];
        #pragma unroll
        for (int i2 = 0; i2 < 4; i2++) v[i2] = r4[i2 * 32 + lane];

        float acc[H_];
        #pragma unroll
        for (int h = 0; h < H_; h++) acc[h] = 0.f;

        #pragma unroll
        for (int i2 = 0; i2 < 4; i2++) {
            #pragma unroll
            for (int h = 0; h < H_; h++) {
                float4 q = q_s4[h * 128 + i2 * 32 + lane];
                acc[h] = fmaf(v[i2].x, q.x, acc[h]);
                acc[h] = fmaf(v[i2].y, q.y, acc[h]);
                acc[h] = fmaf(v[i2].z, q.z, acc[h]);
                acc[h] = fmaf(v[i2].w, q.w, acc[h]);
            }
        }
        #pragma unroll
        for (int h = 0; h < H_; h++) {
            float a = acc[h];
            #pragma unroll
            for (int o = 16; o > 0; o >>= 1) a += __shfl_xor_sync(0xFFFFFFFFu, a, o);
            acc[h] = a;
        }
        if (lane == 0) {
            #pragma unroll
            for (int h = 0; h < H_; h++)
                g_w[((size_t)b * P_ + p) * H_ + h] = acc[h];
        }
    }
}

// ---------------------------------------------------------------------------
// K1c: fused softmax + pooling.
// Grid (b=32, dg=4), block 128 (4 warps). Block loads raw scores for its b,
// softmaxes in smem (warp handles 2 heads), then pools with p-unroll-8.
//   semantic_tokens[b,h,d] = sum_p softmax(scores)[b,p,h] * patch[b,p,d]
// ---------------------------------------------------------------------------
__global__ __launch_bounds__(128) void k_pool(
    const float* __restrict__ patch,
    float* __restrict__ st_out)        // [B,H,D]
{
    __shared__ float w_s[P_][H_];      // 6.3 KB
    const int b  = blockIdx.x;
    const int dg = blockIdx.y;
    const int tid = threadIdx.x;
    const int warp = tid >> 5;
    const int lane = tid & 31;
    const int d  = dg * 128 + tid;

    for (int i = tid; i < P_ * H_; i += 128) w_s[i / H_][i % H_] = g_w[(size_t)b * P_ * H_ + i];
    __syncthreads();

    // softmax over p for 2 heads per warp
    #pragma unroll
    for (int hs = 0; hs < 2; hs++) {
        const int h = warp * 2 + hs;
        float m = -INFINITY;
        for (int p = lane; p < P_; p += 32) m = fmaxf(m, w_s[p][h]);
        #pragma unroll
        for (int o = 16; o > 0; o >>= 1) m = fmaxf(m, __shfl_xor_sync(0xFFFFFFFFu, m, o));
        float s = 0.f;
        for (int p = lane; p < P_; p += 32) {
            float e = __expf(w_s[p][h] - m);
            w_s[p][h] = e;
            s += e;
        }
        #pragma unroll
        for (int o = 16; o > 0; o >>= 1) s += __shfl_xor_sync(0xFFFFFFFFu, s, o);
        float inv = 1.f / s;
        for (int p = lane; p < P_; p += 32) w_s[p][h] *= inv;
    }
    __syncthreads();

    const float* pb = patch + (size_t)b * P_ * D_;
    float acc[H_];
    #pragma unroll
    for (int h = 0; h < H_; h++) acc[h] = 0.f;

    // unroll-8: 24 full batches of 8 + tail of 4 (196 = 24*8 + 4)
    int p = 0;
    for (int bb = 0; bb < 24; bb++, p += 8) {
        float v[8];
        #pragma unroll
        for (int u = 0; u < 8; u++) v[u] = pb[(size_t)(p + u) * D_ + d];
        #pragma unroll
        for (int u = 0; u < 8; u++) {
            #pragma unroll
            for (int h = 0; h < H_; h++) acc[h] = fmaf(w_s[p + u][h], v[u], acc[h]);
        }
    }
    {
        float v[4];
        #pragma unroll
        for (int u = 0; u < 4; u++) v[u] = pb[(size_t)(p + u) * D_ + d];
        #pragma unroll
        for (int u = 0; u < 4; u++) {
            #pragma unroll
            for (int h = 0; h < H_; h++) acc[h] = fmaf(w_s[p + u][h], v[u], acc[h]);
        }
    }
    #pragma unroll
    for (int h = 0; h < H_; h++)
        st_out[((size_t)b * H_ + h) * D_ + d] = acc[h];
}

// ---------------------------------------------------------------------------
// K3: fused sem + dom projections, 2-e-per-warp version.
// hh in [0,8): psem[b,hh,e] = st[b,hh,:] . sem_W[hh,e,:] + sem_b[hh,e]
// hh == 8  : pd[b,e]       = gf[b,:]    . dom_W[e,:]     + dom_b[e]
// Grid (eg=32, hh=9, bg=4) = 1152 blocks; block 256 (8 warps).
// Block stages st for 8 b's (16 KB). Warp w owns e0=eg*16+2w, e1=e0+1;
// each staged-st LDS.128 feeds FMAs for both e rows (halves LDS traffic).
// ---------------------------------------------------------------------------
__global__ __launch_bounds__(256) void k_semdom(
    const float* __restrict__ st,      // [B,H,D]
    const float* __restrict__ semW,    // [H,D,D]
    const float* __restrict__ semb,    // [H,D]
    const float* __restrict__ gf,      // [B,D]
    const float* __restrict__ domW,    // [D,D]
    const float* __restrict__ domb)    // [D]
{
    __shared__ float4 st4[8][128];     // 16 KB

    const int eg  = blockIdx.x;        // 0..31 -> 16 e each
    const int hh  = blockIdx.y;        // 0..8 (8 == domain)
    const int bg  = blockIdx.z;        // 0..3 -> 8 b each
    const int tid = threadIdx.x;
    const int warp = tid >> 5;
    const int lane = tid & 31;

    const bool is_dom = (hh == H_);
    const float4* src4 = is_dom ? (const float4*)gf : (const float4*)st;
    const float4* W4   = is_dom ? (const float4*)domW
                                : (const float4*)semW + (size_t)hh * D_ * 128;
    const float* bias_p = is_dom ? domb : (semb + hh * D_);
    float* outp = is_dom ? g_pd : g_psem;

    // stage st for b = bg*8 .. bg*8+7 (this hh)
    for (int i = tid; i < 8 * 128; i += 256) {
        int b_loc = i >> 7, d4 = i & 127;
        int b = bg * 8 + b_loc;
        size_t off = is_dom ? ((size_t)b * 128 + d4)
                            : (((size_t)b * H_ + hh) * 128 + d4);
        st4[b_loc][d4] = src4[off];
    }
    __syncthreads();

    const int e0 = eg * 16 + warp * 2;
    const float4* wrow0 = W4 + (size_t)e0 * 128;
    const float4* wrow1 = W4 + (size_t)(e0 + 1) * 128;

    // front-batched coalesced weight loads: MLP=8
    float4 wv0[4], wv1[4];
    #pragma unroll
    for (int it = 0; it < 4; it++) {
        wv0[it] = __ldg(wrow0 + it * 32 + lane);
        wv1[it] = __ldg(wrow1 + it * 32 + lane);
    }

    float acc0[8], acc1[8];
    #pragma unroll
    for (int j = 0; j < 8; j++) { acc0[j] = 0.f; acc1[j] = 0.f; }

    #pragma unroll
    for (int it = 0; it < 4; it++) {
        #pragma unroll
        for (int j = 0; j < 8; j++) {
            float4 s = st4[j][it * 32 + lane];
            acc0[j] = fmaf(wv0[it].x, s.x, acc0[j]);
            acc0[j] = fmaf(wv0[it].y, s.y, acc0[j]);
            acc0[j] = fmaf(wv0[it].z, s.z, acc0[j]);
            acc0[j] = fmaf(wv0[it].w, s.w, acc0[j]);
            acc1[j] = fmaf(wv1[it].x, s.x, acc1[j]);
            acc1[j] = fmaf(wv1[it].y, s.y, acc1[j]);
            acc1[j] = fmaf(wv1[it].z, s.z, acc1[j]);
            acc1[j] = fmaf(wv1[it].w, s.w, acc1[j]);
        }
    }
    #pragma unroll
    for (int j = 0; j < 8; j++) {
        float a0 = acc0[j], a1 = acc1[j];
        #pragma unroll
        for (int o = 16; o > 0; o >>= 1) {
            a0 += __shfl_xor_sync(0xFFFFFFFFu, a0, o);
            a1 += __shfl_xor_sync(0xFFFFFFFFu, a1, o);
        }
        acc0[j] = a0; acc1[j] = a1;
    }
    if (lane == 0) {
        const float bias0 = bias_p[e0];
        const float bias1 = bias_p[e0 + 1];
        #pragma unroll
        for (int j = 0; j < 8; j++) {
            const int b = bg * 8 + j;
            size_t base = is_dom ? ((size_t)b * D_)
                                 : (((size_t)b * H_ + hh) * D_);
            outp[base + e0]     = acc0[j] + bias0;
            outp[base + e0 + 1] = acc1[j] + bias1;
        }
    }
}

// ---------------------------------------------------------------------------
// K4: known_prompts writer (the roofline: ~360 MB of stores).
// Grid (cg=50, b=32) = 1600 blocks; 10 c's per block, flat 55-iter loop
// (14080 float4, no predication waste). Evict-first stores.
//   t=0 : known_prefix[c]  t=1 : pd[b]  t=2..9 : psem[b,h]  t=10 : suffix[c]
// ---------------------------------------------------------------------------
__global__ __launch_bounds__(256) void k_known(
    const float* __restrict__ kpre,    // [C,1,D]
    const float* __restrict__ ksuf,    // [C,1,D]
    float* __restrict__ out)           // [B*C, 11, D]
{
    __shared__ float4 sm4[9 * 128];    // [pd | psem h0..h7], 18 KB

    const int cg = blockIdx.x;         // 0..49 (10 c's each)
    const int b  = blockIdx.y;
    const int tid = threadIdx.x;

    {
        const float4* pd4 = (const float4*)(g_pd + (size_t)b * D_);
        const float4* ps4 = (const float4*)(g_psem + (size_t)b * H_ * D_);
        for (int i = tid; i < 9 * 128; i += 256)
            sm4[i] = (i < 128) ? pd4[i] : ps4[i - 128];
    }
    __syncthreads();

    const int c0 = cg * 10;
    float4* base4 = (float4*)out + ((size_t)b * C_ + c0) * 1408;
    const float4* pre4 = (const float4*)kpre + (size_t)c0 * 128;
    const float4* suf4 = (const float4*)ksuf + (size_t)c0 * 128;

    // 10 rows * 1408 float4 = 14080 = 55 * 256 exactly
    #pragma unroll 5
    for (int i = tid; i < 14080; i += 256) {
        int c_loc = i / 1408;
        int j = i - c_loc * 1408;
        int t = j >> 7, d4 = j & 127;      // warp-uniform t
        float4 v;
        if (t == 0)       v = __ldg(pre4 + c_loc * 128 + d4);
        else if (t == 10) v = __ldg(suf4 + c_loc * 128 + d4);
        else              v = sm4[(t - 1) * 128 + d4];
        __stcs(base4 + i, v);
    }
}

// ---------------------------------------------------------------------------
// K5: unknown_prompts writer. [B, 7, D].
// ---------------------------------------------------------------------------
__global__ __launch_bounds__(256) void k_unk(
    const float* __restrict__ upre,
    const float* __restrict__ usuf,
    const float* __restrict__ ust,     // [U,D]
    float* __restrict__ out)
{
    const int b = blockIdx.x;
    const int tid = threadIdx.x;
    float4* out4 = (float4*)out + (size_t)b * (7 * D_ / 4);  // 896 float4
    const float4* upre4 = (const float4*)upre;
    const float4* usuf4 = (const float4*)usuf;
    const float4* ust4  = (const float4*)ust;
    const float4* pd4   = (const float4*)(g_pd + (size_t)b * D_);

    for (int i = tid; i < 896; i += 256) {
        int t = i >> 7, d4 = i & 127;
        float4 v;
        if (t == 0)      v = upre4[d4];
        else if (t == 1) v = pd4[d4];
        else if (t == 6) v = usuf4[d4];
        else             v = ust4[(t - 2) * 128 + d4];
        out4[i] = v;
    }
}

// ---------------------------------------------------------------------------
extern "C" void kernel_launch(void* const* d_in, const int* in_sizes, int n_in,
                              void* d_out, int out_size)
{
    const float* patch = (const float*)d_in[0];   // [B,P,D]
    const float* gf    = (const float*)d_in[1];   // [B,D]
    const float* qv    = (const float*)d_in[2];   // [H,D]
    const float* domW  = (const float*)d_in[3];   // [D,D]
    const float* domb  = (const float*)d_in[4];   // [D]
    const float* semW  = (const float*)d_in[5];   // [H,D,D]
    const float* semb  = (const float*)d_in[6];   // [H,D]
    const float* ust   = (const float*)d_in[7];   // [U,D]
    const float* kpre  = (const float*)d_in[8];   // [C,1,D]
    const float* ksuf  = (const float*)d_in[9];   // [C,1,D]
    const float* upre  = (const float*)d_in[10];  // [1,D]
    const float* usuf  = (const float*)d_in[11];  // [1,D]

    float* out     = (float*)d_out;
    float* unk_out = out + KNOWN_ELEMS;
    float* st_out  = out + KNOWN_ELEMS + UNK_ELEMS;

    dim3 g1(B_, 7);
    k_scores<<<g1, 256>>>(patch, qv);
    dim3 g1c(B_, 4);
    k_pool<<<g1c, 128>>>(patch, st_out);
    dim3 g3(32, 9, 4);
    k_semdom<<<g3, 256>>>(st_out, semW, semb, gf, domW, domb);
    dim3 g4(50, 32);
    k_known<<<g4, 256>>>(kpre, ksuf, out);
    k_unk<<<B_, 256>>>(upre, usuf, ust, unk_out);
}

// round 14
// speedup vs baseline: 1.9549x; 1.0533x over previous
#include <cuda_runtime.h>
#include <math.h>

#define B_  32
#define P_  196
#define D_  512
#define H_  8
#define U_  4
#define C_  500

#define KNOWN_ELEMS (16000LL * 11 * 512)   // 90,112,000
#define UNK_ELEMS   (32LL * 7 * 512)       // 114,688
#define ST_ELEMS    (32LL * 8 * 512)       // 131,072

// Scratch (device-global, allocation-free)
__device__ float g_pd[B_ * D_];              // projected_domain  [32,512]
__device__ float g_psem[B_ * H_ * D_];       // projected_sem     [32,8,512]
__device__ float g_w[B_ * P_ * H_];          // raw attention scores [32,196,8]
__device__ float g_stp[2 * B_ * H_ * D_];    // pooling partial sums (p halves)

// ---------------------------------------------------------------------------
// K1a: scores[b,p,h] = patch[b,p,:] . q[h,:]   (raw, softmax done in k_pool)
// Grid (b=32, pg=14), block 256 (8 warps). Warp per row, 14 rows per block.
// ---------------------------------------------------------------------------
__global__ __launch_bounds__(256) void k_scores(
    const float* __restrict__ patch,   // [B,P,D]
    const float* __restrict__ qv)      // [H,D]
{
    __shared__ float4 q_s4[H_ * 128];  // 16 KB

    const int b    = blockIdx.x;
    const int pg   = blockIdx.y;       // 0..13, 14 rows each
    const int tid  = threadIdx.x;
    const int warp = tid >> 5;
    const int lane = tid & 31;

    for (int i = tid; i < H_ * 128; i += 256) q_s4[i] = ((const float4*)qv)[i];
    __syncthreads();

    const float4* pb4 = (const float4*)(patch + (size_t)b * P_ * D_);

    #pragma unroll
    for (int it = 0; it < 2; it++) {
        const int row = it * 8 + warp;          // 0..15, valid if < 14
        if (row >= 14) break;
        const int p = pg * 14 + row;
        const float4* r4 = pb4 + (size_t)p * 128;

        // front-batch the 4 row loads (MLP=4)
        float4 v[4];
        #pragma unroll
        for (int i2 = 0; i2 < 4; i2++) v[i2] = r4[i2 * 32 + lane];

        float acc[H_];
        #pragma unroll
        for (int h = 0; h < H_; h++) acc[h] = 0.f;

        #pragma unroll
        for (int i2 = 0; i2 < 4; i2++) {
            #pragma unroll
            for (int h = 0; h < H_; h++) {
                float4 q = q_s4[h * 128 + i2 * 32 + lane];
                acc[h] = fmaf(v[i2].x, q.x, acc[h]);
                acc[h] = fmaf(v[i2].y, q.y, acc[h]);
                acc[h] = fmaf(v[i2].z, q.z, acc[h]);
                acc[h] = fmaf(v[i2].w, q.w, acc[h]);
            }
        }
        #pragma unroll
        for (int h = 0; h < H_; h++) {
            float a = acc[h];
            #pragma unroll
            for (int o = 16; o > 0; o >>= 1) a += __shfl_xor_sync(0xFFFFFFFFu, a, o);
            acc[h] = a;
        }
        if (lane == 0) {
            #pragma unroll
            for (int h = 0; h < H_; h++)
                g_w[((size_t)b * P_ + p) * H_ + h] = acc[h];
        }
    }
}

// ---------------------------------------------------------------------------
// K1c: fused softmax + partial pooling.
// Grid (b=32, dg=4, pz=2), block 128 (4 warps). Each block does the FULL
// softmax (cheap, smem-resident) but pools only its half of p (98 rows),
// writing a partial sum to g_stp[pz]. k_semdom sums the halves.
// ---------------------------------------------------------------------------
__global__ __launch_bounds__(128) void k_pool(
    const float* __restrict__ patch)
{
    __shared__ float w_s[P_][H_];      // 6.3 KB
    const int b  = blockIdx.x;
    const int dg = blockIdx.y;
    const int pz = blockIdx.z;         // 0/1 -> p half
    const int tid = threadIdx.x;
    const int warp = tid >> 5;
    const int lane = tid & 31;
    const int d  = dg * 128 + tid;

    for (int i = tid; i < P_ * H_; i += 128) w_s[i / H_][i % H_] = g_w[(size_t)b * P_ * H_ + i];
    __syncthreads();

    // softmax over all p for 2 heads per warp
    #pragma unroll
    for (int hs = 0; hs < 2; hs++) {
        const int h = warp * 2 + hs;
        float m = -INFINITY;
        for (int p = lane; p < P_; p += 32) m = fmaxf(m, w_s[p][h]);
        #pragma unroll
        for (int o = 16; o > 0; o >>= 1) m = fmaxf(m, __shfl_xor_sync(0xFFFFFFFFu, m, o));
        float s = 0.f;
        for (int p = lane; p < P_; p += 32) {
            float e = __expf(w_s[p][h] - m);
            w_s[p][h] = e;
            s += e;
        }
        #pragma unroll
        for (int o = 16; o > 0; o >>= 1) s += __shfl_xor_sync(0xFFFFFFFFu, s, o);
        float inv = 1.f / s;
        for (int p = lane; p < P_; p += 32) w_s[p][h] *= inv;
    }
    __syncthreads();

    const float* pb = patch + (size_t)b * P_ * D_;
    float acc[H_];
    #pragma unroll
    for (int h = 0; h < H_; h++) acc[h] = 0.f;

    // this block's 98 rows: 12 batches of 8 + 2 tail
    int p = pz * 98;
    for (int bb = 0; bb < 12; bb++, p += 8) {
        float v[8];
        #pragma unroll
        for (int u = 0; u < 8; u++) v[u] = pb[(size_t)(p + u) * D_ + d];
        #pragma unroll
        for (int u = 0; u < 8; u++) {
            #pragma unroll
            for (int h = 0; h < H_; h++) acc[h] = fmaf(w_s[p + u][h], v[u], acc[h]);
        }
    }
    {
        float v0 = pb[(size_t)p * D_ + d];
        float v1 = pb[(size_t)(p + 1) * D_ + d];
        #pragma unroll
        for (int h = 0; h < H_; h++) {
            acc[h] = fmaf(w_s[p][h], v0, acc[h]);
            acc[h] = fmaf(w_s[p + 1][h], v1, acc[h]);
        }
    }
    float* outp = g_stp + (size_t)pz * B_ * H_ * D_;
    #pragma unroll
    for (int h = 0; h < H_; h++)
        outp[((size_t)b * H_ + h) * D_ + d] = acc[h];
}

// ---------------------------------------------------------------------------
// K3: fused sem + dom projections, 2-e-per-warp.
// Stages st = g_stp[0] + g_stp[1] (partial-sum combine); eg==0 blocks also
// emit the final semantic_tokens output rows.
// Grid (eg=32, hh=9, bg=4) = 1152 blocks; block 256 (8 warps).
// ---------------------------------------------------------------------------
__global__ __launch_bounds__(256) void k_semdom(
    float* __restrict__ st_out,        // [B,H,D] (output region)
    const float* __restrict__ semW,    // [H,D,D]
    const float* __restrict__ semb,    // [H,D]
    const float* __restrict__ gf,      // [B,D]
    const float* __restrict__ domW,    // [D,D]
    const float* __restrict__ domb)    // [D]
{
    __shared__ float4 st4[8][128];     // 16 KB

    const int eg  = blockIdx.x;        // 0..31 -> 16 e each
    const int hh  = blockIdx.y;        // 0..8 (8 == domain)
    const int bg  = blockIdx.z;        // 0..3 -> 8 b each
    const int tid = threadIdx.x;
    const int warp = tid >> 5;
    const int lane = tid & 31;

    const bool is_dom = (hh == H_);
    const float4* W4   = is_dom ? (const float4*)domW
                                : (const float4*)semW + (size_t)hh * D_ * 128;
    const float* bias_p = is_dom ? domb : (semb + hh * D_);
    float* outp = is_dom ? g_pd : g_psem;

    // stage source rows for b = bg*8 .. bg*8+7
    if (is_dom) {
        const float4* gf4 = (const float4*)gf;
        for (int i = tid; i < 8 * 128; i += 256) {
            int b_loc = i >> 7, d4 = i & 127;
            st4[b_loc][d4] = gf4[(size_t)(bg * 8 + b_loc) * 128 + d4];
        }
    } else {
        const float4* p0 = (const float4*)g_stp;
        const float4* p1 = (const float4*)(g_stp + (size_t)B_ * H_ * D_);
        float4* sto4 = (float4*)st_out;
        for (int i = tid; i < 8 * 128; i += 256) {
            int b_loc = i >> 7, d4 = i & 127;
            size_t off = (((size_t)(bg * 8 + b_loc)) * H_ + hh) * 128 + d4;
            float4 a = p0[off], c = p1[off];
            float4 s = make_float4(a.x + c.x, a.y + c.y, a.z + c.z, a.w + c.w);
            st4[b_loc][d4] = s;
            if (eg == 0) sto4[off] = s;   // final semantic_tokens output
        }
    }
    __syncthreads();

    const int e0 = eg * 16 + warp * 2;
    const float4* wrow0 = W4 + (size_t)e0 * 128;
    const float4* wrow1 = W4 + (size_t)(e0 + 1) * 128;

    float4 wv0[4], wv1[4];
    #pragma unroll
    for (int it = 0; it < 4; it++) {
        wv0[it] = __ldg(wrow0 + it * 32 + lane);
        wv1[it] = __ldg(wrow1 + it * 32 + lane);
    }

    float acc0[8], acc1[8];
    #pragma unroll
    for (int j = 0; j < 8; j++) { acc0[j] = 0.f; acc1[j] = 0.f; }

    #pragma unroll
    for (int it = 0; it < 4; it++) {
        #pragma unroll
        for (int j = 0; j < 8; j++) {
            float4 s = st4[j][it * 32 + lane];
            acc0[j] = fmaf(wv0[it].x, s.x, acc0[j]);
            acc0[j] = fmaf(wv0[it].y, s.y, acc0[j]);
            acc0[j] = fmaf(wv0[it].z, s.z, acc0[j]);
            acc0[j] = fmaf(wv0[it].w, s.w, acc0[j]);
            acc1[j] = fmaf(wv1[it].x, s.x, acc1[j]);
            acc1[j] = fmaf(wv1[it].y, s.y, acc1[j]);
            acc1[j] = fmaf(wv1[it].z, s.z, acc1[j]);
            acc1[j] = fmaf(wv1[it].w, s.w, acc1[j]);
        }
    }
    #pragma unroll
    for (int j = 0; j < 8; j++) {
        float a0 = acc0[j], a1 = acc1[j];
        #pragma unroll
        for (int o = 16; o > 0; o >>= 1) {
            a0 += __shfl_xor_sync(0xFFFFFFFFu, a0, o);
            a1 += __shfl_xor_sync(0xFFFFFFFFu, a1, o);
        }
        acc0[j] = a0; acc1[j] = a1;
    }
    if (lane == 0) {
        const float bias0 = bias_p[e0];
        const float bias1 = bias_p[e0 + 1];
        #pragma unroll
        for (int j = 0; j < 8; j++) {
            const int b = bg * 8 + j;
            size_t base = is_dom ? ((size_t)b * D_)
                                 : (((size_t)b * H_ + hh) * D_);
            outp[base + e0]     = acc0[j] + bias0;
            outp[base + e0 + 1] = acc1[j] + bias1;
        }
    }
}

// ---------------------------------------------------------------------------
// K4: known_prompts writer (the roofline: ~360 MB of stores) + fused unk.
// Grid (cg=21, b=32); cg<20: 25 c's per block (R1's best-measured shape:
// 640 writer blocks, shift/mask indexing, plain STG). cg==20: unknown_prompts.
//   t=0 : known_prefix[c]  t=1 : pd[b]  t=2..9 : psem[b,h]  t=10 : suffix[c]
// ---------------------------------------------------------------------------
__global__ __launch_bounds__(256) void k_known(
    const float* __restrict__ kpre,    // [C,1,D]
    const float* __restrict__ ksuf,    // [C,1,D]
    const float* __restrict__ upre,    // [1,D]
    const float* __restrict__ usuf,    // [1,D]
    const float* __restrict__ ust,     // [U,D]
    float* __restrict__ out,           // known region  [B*C, 11, D]
    float* __restrict__ unk_out)       // unknown region [B, 7, D]
{
    const int cg = blockIdx.x;         // 0..20
    const int b  = blockIdx.y;
    const int tid = threadIdx.x;

    if (cg == 20) {
        // unknown_prompts for this b: 896 float4
        float4* out4 = (float4*)unk_out + (size_t)b * 896;
        const float4* upre4 = (const float4*)upre;
        const float4* usuf4 = (const float4*)usuf;
        const float4* ust4  = (const float4*)ust;
        const float4* pd4   = (const float4*)(g_pd + (size_t)b * D_);
        for (int i = tid; i < 896; i += 256) {
            int t = i >> 7, d4 = i & 127;
            float4 v;
            if (t == 0)      v = upre4[d4];
            else if (t == 1) v = pd4[d4];
            else if (t == 6) v = usuf4[d4];
            else             v = ust4[(t - 2) * 128 + d4];
            out4[i] = v;
        }
        return;
    }

    __shared__ float4 sm4[9 * 128];    // [pd | psem h0..h7], 18 KB
    {
        const float4* pd4 = (const float4*)(g_pd + (size_t)b * D_);
        const float4* ps4 = (const float4*)(g_psem + (size_t)b * H_ * D_);
        for (int i = tid; i < 9 * 128; i += 256)
            sm4[i] = (i < 128) ? pd4[i] : ps4[i - 128];
    }
    __syncthreads();

    float4* out4 = (float4*)out;
    const float4* pre4 = (const float4*)kpre;
    const float4* suf4 = (const float4*)ksuf;

    for (int cc = 0; cc < 25; cc++) {
        const int c = cg * 25 + cc;
        const size_t r = (size_t)b * C_ + c;
        float4* row4 = out4 + r * 1408;             // 11*512/4 per row
        const float4* p4 = pre4 + (size_t)c * 128;
        const float4* s4 = suf4 + (size_t)c * 128;
        #pragma unroll
        for (int k = 0; k < 6; k++) {
            int i = tid + k * 256;
            if (i < 1408) {
                int t = i >> 7, d4 = i & 127;       // warp-uniform t
                float4 v;
                if (t == 0)       v = __ldg(p4 + d4);
                else if (t == 10) v = __ldg(s4 + d4);
                else              v = sm4[(t - 1) * 128 + d4];
                row4[i] = v;
            }
        }
    }
}

// ---------------------------------------------------------------------------
extern "C" void kernel_launch(void* const* d_in, const int* in_sizes, int n_in,
                              void* d_out, int out_size)
{
    const float* patch = (const float*)d_in[0];   // [B,P,D]
    const float* gf    = (const float*)d_in[1];   // [B,D]
    const float* qv    = (const float*)d_in[2];   // [H,D]
    const float* domW  = (const float*)d_in[3];   // [D,D]
    const float* domb  = (const float*)d_in[4];   // [D]
    const float* semW  = (const float*)d_in[5];   // [H,D,D]
    const float* semb  = (const float*)d_in[6];   // [H,D]
    const float* ust   = (const float*)d_in[7];   // [U,D]
    const float* kpre  = (const float*)d_in[8];   // [C,1,D]
    const float* ksuf  = (const float*)d_in[9];   // [C,1,D]
    const float* upre  = (const float*)d_in[10];  // [1,D]
    const float* usuf  = (const float*)d_in[11];  // [1,D]

    float* out     = (float*)d_out;
    float* unk_out = out + KNOWN_ELEMS;
    float* st_out  = out + KNOWN_ELEMS + UNK_ELEMS;

    dim3 g1(B_, 14);
    k_scores<<<g1, 256>>>(patch, qv);
    dim3 g1c(B_, 4, 2);
    k_pool<<<g1c, 128>>>(patch);
    dim3 g3(32, 9, 4);
    k_semdom<<<g3, 256>>>(st_out, semW, semb, gf, domW, domb);
    dim3 g4(21, 32);
    k_known<<<g4, 256>>>(kpre, ksuf, upre, usuf, ust, out, unk_out);
}